// round 14
// baseline (speedup 1.0000x reference)
#include <cuda_runtime.h>
#include <cuda_fp16.h>
#include <cstdint>

// SharedGroupLinearLayer via single-pass fp16 mma.sync — BARRIER-FREE main loop.
// out = x@Wcat + EB[tok%16] combined by gate: out = h1 + a0*hd,
//   a0 = sigmoid(x·rwd + ec[tok%16]),  EB1 = e@W1^T+b1, EBd = e@Wd^T+bd.
// A-fragments are assembled DIRECTLY in registers from coalesced LDG.64
// (PTX m16n8k16 A layout: rows g,g+8; k pairs 2c,2c+1 and 2c+8,2c+9 per
// 16-k tile) — no STS, no ldmatrix, no smem A tile, no __syncthreads in loop.
// EB init values and ec live in registers (thread rows are tile-invariant).

#define THREADS 256
#define TILE_M  64
#define NTILES  4096
#define GRID    304

// smem offsets
#define W_OFF    0        // 16KB W fp16 staging (init only, for B ldsm)
#define EB1_OFF  16384    // 16x64 f32: e@W1^T + b1   (column-permuted o)
#define EBD_OFF  20480    // 16x64 f32: e@Wd^T + bd   (column-permuted o)
#define RWD_OFF  24576    // 64 f32
#define EC_OFF   24832    // 16 f32: e@rwd
#define SMEM_TOTAL 24896

__device__ __forceinline__ uint32_t smem_u32(const void* p) {
    uint32_t a;
    asm("{ .reg .u64 t; cvta.to.shared.u64 t, %1; cvt.u32.u64 %0, t; }" : "=r"(a) : "l"(p));
    return a;
}
// pack two f32 -> f16x2 word: low 16 = first arg, high = second
__device__ __forceinline__ uint32_t cvt2h(float lo, float hi) {
    uint32_t r;
    asm("cvt.rn.f16x2.f32 %0, %1, %2;" : "=r"(r) : "f"(hi), "f"(lo));
    return r;
}
__device__ __forceinline__ void ldsm_x2(uint32_t* r, uint32_t addr) {
    asm volatile("ldmatrix.sync.aligned.m8n8.x2.shared.b16 {%0,%1}, [%2];"
        : "=r"(r[0]), "=r"(r[1]) : "r"(addr));
}
__device__ __forceinline__ void mma_f16(float* d, const uint32_t* a, const uint32_t* b) {
    asm volatile("mma.sync.aligned.m16n8k16.row.col.f32.f16.f16.f32 "
        "{%0,%1,%2,%3}, {%4,%5,%6,%7}, {%8,%9}, {%0,%1,%2,%3};"
        : "+f"(d[0]), "+f"(d[1]), "+f"(d[2]), "+f"(d[3])
        : "r"(a[0]), "r"(a[1]), "r"(a[2]), "r"(a[3]), "r"(b[0]), "r"(b[1]));
}

__global__ __launch_bounds__(THREADS, 2)
void sgl_fp16e_kernel(const float* __restrict__ x,
                      const float* __restrict__ emb,
                      const float* __restrict__ read_w,
                      const float* __restrict__ w_stack,
                      const float* __restrict__ b_stack,
                      float* __restrict__ out)
{
    extern __shared__ __align__(1024) char smem[];
    const uint32_t sb = smem_u32(smem);

    const int tid  = threadIdx.x;
    const int lane = tid & 31;
    const int wid  = tid >> 5;
    const int q    = wid & 3;      // n-column group
    const int r    = wid >> 2;     // m-half (tokens r*32..r*32+31)

    float* rwd_s = (float*)(smem + RWD_OFF);
    float* eb1_s = (float*)(smem + EB1_OFF);
    float* ebd_s = (float*)(smem + EBD_OFF);
    float* ec_s  = (float*)(smem + EC_OFF);

    // ---- init: rwd first (ec needs it) ----
    for (int i = tid; i < 64; i += THREADS)
        rwd_s[i] = read_w[2 * i] - read_w[2 * i + 1];
    __syncthreads();

    // W fp16 staging, column-permuted: smem row n <- output o so thread
    // (q,tc) owns 4 contiguous outputs 16q+4tc..+3. Row = 128B, XOR-swizzled.
    for (int i = tid; i < 128 * 32; i += THREADS) {
        int n = i >> 5, kp = (i & 31) * 2;
        int half = n >> 6;              // 0: W1, 1: W0-W1
        int nn = n & 63;
        int p = nn & 7, t = (nn >> 3) & 1;
        int o = (nn & 48) + ((p >> 1) << 2) + 2 * t + (p & 1);
        float v0, v1;
        if (half == 0) {
            v0 = w_stack[4096 + o * 64 + kp];
            v1 = w_stack[4096 + o * 64 + kp + 1];
        } else {
            v0 = w_stack[o * 64 + kp]     - w_stack[4096 + o * 64 + kp];
            v1 = w_stack[o * 64 + kp + 1] - w_stack[4096 + o * 64 + kp + 1];
        }
        int off = n * 128 + (((kp >> 3) ^ (n & 7)) << 4) + (kp & 7) * 2;
        *(uint32_t*)(smem + W_OFF + off) = cvt2h(v0, v1);
    }

    // EB tables with the SAME column permutation (o index below is the true
    // weight output column; stored at permuted position matching epilogue o0).
    // EB1[nb][oP] = e[nb]·W1[o] + b1[o];  EBd[nb][oP] = e[nb]·Wd[o] + bd[o].
    // Our epilogue indexes eb tables by the PERMUTED o0 and stores to out[o0],
    // and W staging maps smem row n(perm of o) — but out columns are the TRUE
    // o. Since permutation maps thread->o0 = its true output set (verified in
    // R7-R13 end-to-end), EB must be indexed by TRUE o. Store EB at [nb][o].
    for (int i = tid; i < 16 * 64; i += THREADS) {
        int nb = i >> 6, o = i & 63;
        const float* ep  = emb + nb * 64;
        const float* w1p = w_stack + 4096 + o * 64;
        const float* w0p = w_stack + o * 64;
        float s1 = 0.f, s0 = 0.f;
        #pragma unroll 8
        for (int k = 0; k < 64; k++) { s1 += ep[k] * w1p[k]; s0 += ep[k] * w0p[k]; }
        float b1 = b_stack[64 + o];
        eb1_s[i] = s1 + b1;
        ebd_s[i] = (s0 - s1) + (b_stack[o] - b1);
    }
    if (tid < 16) {
        const float* ep = emb + tid * 64;
        float s = 0.f;
        #pragma unroll 8
        for (int k = 0; k < 64; k++) s += ep[k] * rwd_s[k];
        ec_s[tid] = s;
    }
    __syncthreads();

    // ---- B fragments -> registers (kept for whole kernel) ----
    uint32_t B[4][4][2];
    #pragma unroll
    for (int nti = 0; nti < 4; nti++) {
        int nt = 2 * q + (nti & 1) + ((nti >> 1) << 3);
        #pragma unroll
        for (int k = 0; k < 4; k++) {
            int row  = nt * 8 + (lane & 7);
            int unit = k * 2 + ((lane >> 3) & 1);
            ldsm_x2(B[nti][k], sb + W_OFF + row * 128 + ((unit ^ (row & 7)) << 4));
        }
    }

    const int grp = lane >> 2, c = lane & 3;
    const int o0  = 16 * q + 4 * c;

    // EB init values + gate constants -> registers (tile-invariant rows)
    const float4 eb1_g  = *(const float4*)&eb1_s[grp * 64 + o0];
    const float4 eb1_g8 = *(const float4*)&eb1_s[(grp + 8) * 64 + o0];
    const float4 ebd_g  = *(const float4*)&ebd_s[grp * 64 + o0];
    const float4 ebd_g8 = *(const float4*)&ebd_s[(grp + 8) * 64 + o0];
    const float  ec0 = ec_s[grp];
    const float  ec1 = ec_s[grp + 8];

    // ---------------- barrier-free main loop ----------------
    for (int tile = blockIdx.x; tile < NTILES; tile += GRID)
    {
        float acc[2][4][4];
        #pragma unroll
        for (int m = 0; m < 2; m++) {
            acc[m][0][0] = eb1_g.x;  acc[m][0][1] = eb1_g.y;
            acc[m][1][0] = eb1_g.z;  acc[m][1][1] = eb1_g.w;
            acc[m][0][2] = eb1_g8.x; acc[m][0][3] = eb1_g8.y;
            acc[m][1][2] = eb1_g8.z; acc[m][1][3] = eb1_g8.w;
            acc[m][2][0] = ebd_g.x;  acc[m][2][1] = ebd_g.y;
            acc[m][3][0] = ebd_g.z;  acc[m][3][1] = ebd_g.w;
            acc[m][2][2] = ebd_g8.x; acc[m][2][3] = ebd_g8.y;
            acc[m][3][2] = ebd_g8.z; acc[m][3][3] = ebd_g8.w;
        }
        float a0v[2][2];

        #pragma unroll
        for (int m = 0; m < 2; m++) {
            const int t0 = r * 32 + m * 16 + grp;
            const float* xr0 = x + ((size_t)tile * 64 + t0) * 64;
            const float* xr1 = xr0 + 8 * 64;

            // build A fragments in registers + gate partials
            uint32_t frag[4][4];
            float g0 = 0.f, g1 = 0.f;
            #pragma unroll
            for (int kt = 0; kt < 4; kt++) {
                const int k0 = kt * 16 + 2 * c;
                float2 p00 = *(const float2*)(xr0 + k0);
                float2 p01 = *(const float2*)(xr0 + k0 + 8);
                float2 p10 = *(const float2*)(xr1 + k0);
                float2 p11 = *(const float2*)(xr1 + k0 + 8);
                float2 w0 = *(const float2*)(rwd_s + k0);
                float2 w8 = *(const float2*)(rwd_s + k0 + 8);
                g0 += p00.x * w0.x + p00.y * w0.y + p01.x * w8.x + p01.y * w8.y;
                g1 += p10.x * w0.x + p10.y * w0.y + p11.x * w8.x + p11.y * w8.y;
                frag[kt][0] = cvt2h(p00.x, p00.y);   // row g,   k 2c,2c+1
                frag[kt][1] = cvt2h(p10.x, p10.y);   // row g+8, k 2c,2c+1
                frag[kt][2] = cvt2h(p01.x, p01.y);   // row g,   k 2c+8,2c+9
                frag[kt][3] = cvt2h(p11.x, p11.y);   // row g+8, k 2c+8,2c+9
            }
            // gate reduce over the 4 lanes of the group
            g0 += __shfl_xor_sync(0xffffffffu, g0, 1);
            g0 += __shfl_xor_sync(0xffffffffu, g0, 2);
            g1 += __shfl_xor_sync(0xffffffffu, g1, 1);
            g1 += __shfl_xor_sync(0xffffffffu, g1, 2);
            a0v[m][0] = 1.f / (1.f + __expf(-(g0 + ec0)));
            a0v[m][1] = 1.f / (1.f + __expf(-(g1 + ec1)));

            // MMA for this m (frees frag regs before next m)
            #pragma unroll
            for (int kt = 0; kt < 4; kt++) {
                mma_f16(acc[m][0], frag[kt], B[0][kt]);
                mma_f16(acc[m][1], frag[kt], B[1][kt]);
                mma_f16(acc[m][2], frag[kt], B[2][kt]);
                mma_f16(acc[m][3], frag[kt], B[3][kt]);
            }
        }

        // ---- epilogue: gate combine + STG.128 (EB already in acc) ----
        {
            float* outb = out + (size_t)tile * (TILE_M * 64);
            #pragma unroll
            for (int m = 0; m < 2; m++) {
                int t0 = r * 32 + m * 16 + grp;
                int t1 = t0 + 8;
                float a00 = a0v[m][0];
                float a01 = a0v[m][1];
                float4 w;
                w.x = fmaf(a00, acc[m][2][0], acc[m][0][0]);
                w.y = fmaf(a00, acc[m][2][1], acc[m][0][1]);
                w.z = fmaf(a00, acc[m][3][0], acc[m][1][0]);
                w.w = fmaf(a00, acc[m][3][1], acc[m][1][1]);
                *(float4*)&outb[t0 * 64 + o0] = w;
                w.x = fmaf(a01, acc[m][2][2], acc[m][0][2]);
                w.y = fmaf(a01, acc[m][2][3], acc[m][0][3]);
                w.z = fmaf(a01, acc[m][3][2], acc[m][1][2]);
                w.w = fmaf(a01, acc[m][3][3], acc[m][1][3]);
                *(float4*)&outb[t1 * 64 + o0] = w;
            }
        }
    }
}

extern "C" void kernel_launch(void* const* d_in, const int* in_sizes, int n_in,
                              void* d_out, int out_size)
{
    const float* x       = (const float*)d_in[0];
    const float* emb     = (const float*)d_in[1];
    const float* read_w  = (const float*)d_in[2];
    const float* w_stack = (const float*)d_in[3];
    const float* b_stack = (const float*)d_in[4];
    float* out = (float*)d_out;

    cudaFuncSetAttribute(sgl_fp16e_kernel, cudaFuncAttributeMaxDynamicSharedMemorySize, SMEM_TOTAL);
    sgl_fp16e_kernel<<<GRID, THREADS, SMEM_TOTAL>>>(x, emb, read_w, w_stack, b_stack, out);
}

// round 15
// speedup vs baseline: 1.1483x; 1.1483x over previous
#include <cuda_runtime.h>
#include <cuda_fp16.h>
#include <cstdint>

// SharedGroupLinearLayer via single-pass fp16 mma.sync, 2 CTAs/SM (R10 base).
// out = x·Wcat^T + EB[tok%16], combined: out = h1 + a0*hd,
//   a0 = sigmoid(x·rwd + ec[tok%16]);  EB1 = e·W1^T+b1, EBd = e·Wd^T+bd.
// Round 15: R10 structure (cp.async raw staging, 2 barriers/tile, B in regs)
// with emb/bias folded into register-resident accumulator-init tables (EB)
// and gate constant ec — convert loses emb LDS+FADDs, epilogue loses bias.

#define THREADS 256
#define TILE_M  64
#define NTILES  4096
#define GRID    304

#define RAW_PITCH 320     // 256B + 64B pad: conflict-free 4-thr/token reads

// dynamic smem offsets
#define RAW_OFF  0        // 2 x 20480B raw x (64 tok x 320B); init: W fp16 tile
#define AB_OFF   40960    // 8KB fp16 A tile (64 tok x 128B)
#define EB1_OFF  49152    // 16x64 f32: e·W1^T + b1
#define EBD_OFF  53248    // 16x64 f32: e·Wd^T + bd
#define RWD_OFF  57344    // 64 f32
#define EC_OFF   57600    // 16 f32: e·rwd
#define A0_OFF   57664    // 64 f32 gate (sigmoid applied)
#define SMEM_TOTAL 57920

__device__ __forceinline__ uint32_t smem_u32(const void* p) {
    uint32_t a;
    asm("{ .reg .u64 t; cvta.to.shared.u64 t, %1; cvt.u32.u64 %0, t; }" : "=r"(a) : "l"(p));
    return a;
}
// pack two f32 -> f16x2 word: low 16 = first arg, high = second
__device__ __forceinline__ uint32_t cvt2h(float lo, float hi) {
    uint32_t r;
    asm("cvt.rn.f16x2.f32 %0, %1, %2;" : "=r"(r) : "f"(hi), "f"(lo));
    return r;
}
__device__ __forceinline__ void ldsm_x4(uint32_t* r, uint32_t addr) {
    asm volatile("ldmatrix.sync.aligned.m8n8.x4.shared.b16 {%0,%1,%2,%3}, [%4];"
        : "=r"(r[0]), "=r"(r[1]), "=r"(r[2]), "=r"(r[3]) : "r"(addr));
}
__device__ __forceinline__ void ldsm_x2(uint32_t* r, uint32_t addr) {
    asm volatile("ldmatrix.sync.aligned.m8n8.x2.shared.b16 {%0,%1}, [%2];"
        : "=r"(r[0]), "=r"(r[1]) : "r"(addr));
}
__device__ __forceinline__ void mma_f16(float* d, const uint32_t* a, const uint32_t* b) {
    asm volatile("mma.sync.aligned.m16n8k16.row.col.f32.f16.f16.f32 "
        "{%0,%1,%2,%3}, {%4,%5,%6,%7}, {%8,%9}, {%0,%1,%2,%3};"
        : "+f"(d[0]), "+f"(d[1]), "+f"(d[2]), "+f"(d[3])
        : "r"(a[0]), "r"(a[1]), "r"(a[2]), "r"(a[3]), "r"(b[0]), "r"(b[1]));
}
__device__ __forceinline__ void cp_async16(uint32_t daddr, const void* gptr) {
    asm volatile("cp.async.ca.shared.global [%0], [%1], 16;" :: "r"(daddr), "l"(gptr));
}
#define CP_COMMIT() asm volatile("cp.async.commit_group;" ::: "memory")
#define CP_WAIT1()  asm volatile("cp.async.wait_group 1;" ::: "memory")

__global__ __launch_bounds__(THREADS, 2)
void sgl_fp16f_kernel(const float* __restrict__ x,
                      const float* __restrict__ emb,
                      const float* __restrict__ read_w,
                      const float* __restrict__ w_stack,
                      const float* __restrict__ b_stack,
                      float* __restrict__ out)
{
    extern __shared__ __align__(1024) char smem[];
    const uint32_t sb = smem_u32(smem);

    const int tid  = threadIdx.x;
    const int lane = tid & 31;
    const int wid  = tid >> 5;
    const int q    = wid & 3;      // n-column group
    const int r    = wid >> 2;     // m-half (tokens r*32..r*32+31)

    float* rwd_s = (float*)(smem + RWD_OFF);
    float* eb1_s = (float*)(smem + EB1_OFF);
    float* ebd_s = (float*)(smem + EBD_OFF);
    float* ec_s  = (float*)(smem + EC_OFF);
    float* a0_s  = (float*)(smem + A0_OFF);

    // ---- one-time setup: rwd first (ec needs it) ----
    for (int i = tid; i < 64; i += THREADS)
        rwd_s[i] = read_w[2 * i] - read_w[2 * i + 1];
    __syncthreads();

    // W fp16 staged in RAW area, column-permuted so thread (q,tc) owns
    // 4 contiguous outputs 16q+4tc..+3. Row n = 128B, XOR-swizzled 16B units.
    for (int i = tid; i < 128 * 32; i += THREADS) {
        int n = i >> 5, kp = (i & 31) * 2;
        int half = n >> 6;              // 0: W1, 1: W0-W1
        int nn = n & 63;
        int p = nn & 7, t = (nn >> 3) & 1;
        int o = (nn & 48) + ((p >> 1) << 2) + 2 * t + (p & 1);
        float v0, v1;
        if (half == 0) {
            v0 = w_stack[4096 + o * 64 + kp];
            v1 = w_stack[4096 + o * 64 + kp + 1];
        } else {
            v0 = w_stack[o * 64 + kp]     - w_stack[4096 + o * 64 + kp];
            v1 = w_stack[o * 64 + kp + 1] - w_stack[4096 + o * 64 + kp + 1];
        }
        int off = n * 128 + (((kp >> 3) ^ (n & 7)) << 4) + (kp & 7) * 2;
        *(uint32_t*)(smem + RAW_OFF + off) = cvt2h(v0, v1);
    }

    // EB tables (true output index o): EB1[nb][o] = e[nb]·W1[o] + b1[o];
    // EBd[nb][o] = e[nb]·(W0-W1)[o] + (b0-b1)[o].  ec[nb] = e[nb]·rwd.
    for (int i = tid; i < 16 * 64; i += THREADS) {
        int nb = i >> 6, o = i & 63;
        const float* ep  = emb + nb * 64;
        const float* w1p = w_stack + 4096 + o * 64;
        const float* w0p = w_stack + o * 64;
        float s1 = 0.f, s0 = 0.f;
        #pragma unroll 8
        for (int k = 0; k < 64; k++) { s1 += ep[k] * w1p[k]; s0 += ep[k] * w0p[k]; }
        float b1 = b_stack[64 + o];
        eb1_s[i] = s1 + b1;
        ebd_s[i] = (s0 - s1) + (b_stack[o] - b1);
    }
    if (tid < 16) {
        const float* ep = emb + tid * 64;
        float s = 0.f;
        #pragma unroll 8
        for (int k = 0; k < 64; k++) s += ep[k] * rwd_s[k];
        ec_s[tid] = s;
    }
    __syncthreads();

    // ---- B fragments -> registers (kept for whole kernel) ----
    uint32_t B[4][4][2];
    #pragma unroll
    for (int nti = 0; nti < 4; nti++) {
        int nt = 2 * q + (nti & 1) + ((nti >> 1) << 3);
        #pragma unroll
        for (int k = 0; k < 4; k++) {
            int row  = nt * 8 + (lane & 7);
            int unit = k * 2 + ((lane >> 3) & 1);
            ldsm_x2(B[nti][k], sb + RAW_OFF + row * 128 + ((unit ^ (row & 7)) << 4));
        }
    }

    const int grp = lane >> 2, tc = lane & 3;
    const int o0  = 16 * q + 4 * tc;
    const int ct  = tid >> 2;        // convert token (0..63)
    const int cp  = tid & 3;         // convert part (4 chunks each)

    // EB init values + gate constant -> registers (token%16 is thread-fixed)
    const float4 eb1_g  = *(const float4*)&eb1_s[grp * 64 + o0];
    const float4 eb1_g8 = *(const float4*)&eb1_s[(grp + 8) * 64 + o0];
    const float4 ebd_g  = *(const float4*)&ebd_s[grp * 64 + o0];
    const float4 ebd_g8 = *(const float4*)&ebd_s[(grp + 8) * 64 + o0];
    const float  ecv    = ec_s[ct & 15];

    __syncthreads();   // RAW area (W staging) free for x after B-frag loads

    // ---- prologue: stage first tile's x ----
    {
        const float4* src = (const float4*)x + (size_t)blockIdx.x * (TILE_M * 64 / 4);
        #pragma unroll
        for (int k = 0; k < 4; k++) {
            int j = tid + k * THREADS;
            int t = j >> 4, c = j & 15;
            cp_async16(sb + RAW_OFF + t * RAW_PITCH + c * 16, src + j);
        }
    }
    CP_COMMIT();

    int buf = 0;
    for (int tile = blockIdx.x; tile < NTILES; tile += GRID)
    {
        // prefetch next tile into other raw buffer
        {
            int nt = tile + GRID;
            if (nt < NTILES) {
                const float4* src = (const float4*)x + (size_t)nt * (TILE_M * 64 / 4);
                uint32_t dst = sb + RAW_OFF + (buf ^ 1) * 20480;
                #pragma unroll
                for (int k = 0; k < 4; k++) {
                    int j = tid + k * THREADS;
                    int t = j >> 4, c = j & 15;
                    cp_async16(dst + t * RAW_PITCH + c * 16, src + j);
                }
            }
        }
        CP_COMMIT();
        CP_WAIT1();          // current tile's copy complete
        __syncthreads();     // + separates prev MMA reads from A rewrite

        // ---- convert: 4 threads/token, gate + fp16 pack (no emb work) ----
        {
            const char* rawb = smem + RAW_OFF + buf * 20480 + ct * RAW_PITCH;
            float g = 0.f;
            uint2 hw[4];
            #pragma unroll
            for (int i = 0; i < 4; i++) {
                int c = cp + 4 * i;
                float4 v = *(const float4*)(rawb + c * 16);
                const float* rp = &rwd_s[c * 4];
                g += v.x * rp[0] + v.y * rp[1] + v.z * rp[2] + v.w * rp[3];
                hw[i].x = cvt2h(v.x, v.y);
                hw[i].y = cvt2h(v.z, v.w);
            }
            g += __shfl_xor_sync(0xffffffffu, g, 1);
            g += __shfl_xor_sync(0xffffffffu, g, 2);
            if (cp == 0) a0_s[ct] = 1.f / (1.f + __expf(-(g + ecv)));
            #pragma unroll
            for (int i = 0; i < 4; i++) {
                int c = cp + 4 * i;
                uint32_t off = (uint32_t)(ct * 128 + (((c >> 1) ^ (ct & 7)) << 4) + (c & 1) * 8);
                *(uint2*)(smem + AB_OFF + off) = hw[i];
            }
        }
        __syncthreads();

        // ---- MMA: single fp16 pass; acc initialized with EB tables ----
        float acc[2][4][4];
        #pragma unroll
        for (int m = 0; m < 2; m++) {
            acc[m][0][0] = eb1_g.x;  acc[m][0][1] = eb1_g.y;
            acc[m][0][2] = eb1_g8.x; acc[m][0][3] = eb1_g8.y;
            acc[m][1][0] = eb1_g.z;  acc[m][1][1] = eb1_g.w;
            acc[m][1][2] = eb1_g8.z; acc[m][1][3] = eb1_g8.w;
            acc[m][2][0] = ebd_g.x;  acc[m][2][1] = ebd_g.y;
            acc[m][2][2] = ebd_g8.x; acc[m][2][3] = ebd_g8.y;
            acc[m][3][0] = ebd_g.z;  acc[m][3][1] = ebd_g.w;
            acc[m][3][2] = ebd_g8.z; acc[m][3][3] = ebd_g8.w;
        }

        #pragma unroll
        for (int k = 0; k < 4; k++) {
            #pragma unroll
            for (int m = 0; m < 2; m++) {
                int tok  = r * 32 + m * 16 + (lane & 15);
                int unit = k * 2 + (lane >> 4);
                uint32_t aaddr = sb + AB_OFF + tok * 128 + ((unit ^ (tok & 7)) << 4);
                uint32_t A[4];
                ldsm_x4(A, aaddr);
                mma_f16(acc[m][0], A, B[0][k]);
                mma_f16(acc[m][1], A, B[1][k]);
                mma_f16(acc[m][2], A, B[2][k]);
                mma_f16(acc[m][3], A, B[3][k]);
            }
        }

        // ---- epilogue: gate combine + STG.128 (EB already in acc) ----
        {
            float* outb = out + (size_t)tile * (TILE_M * 64);
            #pragma unroll
            for (int m = 0; m < 2; m++) {
                int t0 = r * 32 + m * 16 + grp;
                int t1 = t0 + 8;
                float a00 = a0_s[t0];
                float a01 = a0_s[t1];
                float4 w;
                w.x = fmaf(a00, acc[m][2][0], acc[m][0][0]);
                w.y = fmaf(a00, acc[m][2][1], acc[m][0][1]);
                w.z = fmaf(a00, acc[m][3][0], acc[m][1][0]);
                w.w = fmaf(a00, acc[m][3][1], acc[m][1][1]);
                *(float4*)&outb[t0 * 64 + o0] = w;
                w.x = fmaf(a01, acc[m][2][2], acc[m][0][2]);
                w.y = fmaf(a01, acc[m][2][3], acc[m][0][3]);
                w.z = fmaf(a01, acc[m][3][2], acc[m][1][2]);
                w.w = fmaf(a01, acc[m][3][3], acc[m][1][3]);
                *(float4*)&outb[t1 * 64 + o0] = w;
            }
        }
        buf ^= 1;
        // next iteration's top __syncthreads separates this MMA/epilogue
        // from the next convert's A-tile rewrite.
    }
}

extern "C" void kernel_launch(void* const* d_in, const int* in_sizes, int n_in,
                              void* d_out, int out_size)
{
    const float* x       = (const float*)d_in[0];
    const float* emb     = (const float*)d_in[1];
    const float* read_w  = (const float*)d_in[2];
    const float* w_stack = (const float*)d_in[3];
    const float* b_stack = (const float*)d_in[4];
    float* out = (float*)d_out;

    cudaFuncSetAttribute(sgl_fp16f_kernel, cudaFuncAttributeMaxDynamicSharedMemorySize, SMEM_TOTAL);
    sgl_fp16f_kernel<<<GRID, THREADS, SMEM_TOTAL>>>(x, emb, read_w, w_stack, b_stack, out);
}